// round 3
// baseline (speedup 1.0000x reference)
#include <cuda_runtime.h>

// Problem constants (fixed by the reference)
#define N_SAE  128
#define D_DATA 128
#define D_DICT 512
#define BATCH  1024
#define CAP    64     // max tokens per expert (mean 16; overflow prob ~0)
#define CHUNK  8      // tokens per compute CTA

typedef unsigned long long u64;

// Device scratch
__device__ int   g_cnt [N_SAE];               // per-expert pair count
__device__ int   g_tcnt[BATCH];               // per-token slot counter (j in {0,1})
__device__ int   g_pair[N_SAE * CAP];         // pair id = token*2 + j
__device__ float g_gv  [N_SAE * CAP];
__device__ float g_stage[BATCH * 2 * D_DATA]; // per-pair decode output (1 MB)

// ---------------- f32x2 packed helpers (sm_103a) ----------------
__device__ __forceinline__ u64 pk(float lo, float hi) {
    u64 r; asm("mov.b64 %0,{%1,%2};" : "=l"(r) : "f"(lo), "f"(hi)); return r;
}
__device__ __forceinline__ void upk(float& lo, float& hi, u64 v) {
    asm("mov.b64 {%0,%1},%2;" : "=f"(lo), "=f"(hi) : "l"(v));
}
__device__ __forceinline__ u64 fma2(u64 a, u64 b, u64 c) {
    u64 d; asm("fma.rn.f32x2 %0,%1,%2,%3;" : "=l"(d) : "l"(a), "l"(b), "l"(c)); return d;
}
__device__ __forceinline__ u64 add2(u64 a, u64 b) {
    u64 d; asm("add.rn.f32x2 %0,%1,%2;" : "=l"(d) : "l"(a), "l"(b)); return d;
}
__device__ __forceinline__ u64 mul2(u64 a, u64 b) {
    u64 d; asm("mul.rn.f32x2 %0,%1,%2;" : "=l"(d) : "l"(a), "l"(b)); return d;
}
__device__ __forceinline__ u64 relu2(u64 v) {
    float lo, hi; upk(lo, hi, v);
    return pk(fmaxf(lo, 0.0f), fmaxf(hi, 0.0f));
}

// ---------------------------------------------------------------------------
// Kernel 1: build per-expert pair lists. 16 blocks x 512 threads, float4 reads.
// j = per-token slot via atomic counter (order-independent: combine just sums).
// ---------------------------------------------------------------------------
__global__ void k_build(const float* __restrict__ gate) {
    int i = blockIdx.x * 512 + threadIdx.x;          // 0..8191
    const float4* g4 = (const float4*)gate;
    #pragma unroll
    for (int u = 0; u < 4; u++) {
        int q = i + u * 8192;                         // float4 index 0..32767
        float4 v = g4[q];
        float vals[4] = {v.x, v.y, v.z, v.w};
        #pragma unroll
        for (int c = 0; c < 4; c++) {
            float val = vals[c];
            if (val != 0.0f) {
                int fi = q * 4 + c;
                int b = fi >> 7, e = fi & 127;
                int j    = atomicAdd(&g_tcnt[b], 1);
                int slot = atomicAdd(&g_cnt[e], 1);
                if (slot < CAP) {
                    g_pair[e * CAP + slot] = b * 2 + j;
                    g_gv [e * CAP + slot] = val;
                }
            }
        }
    }
}

// ---------------------------------------------------------------------------
// Kernel 2: fused encode -> relu -> gate -> decode, staged per-pair output.
// grid = (N_SAE, CAP/CHUNK), 512 threads.
// Weights are loaded as NATURAL adjacent pairs (LDG.64 -> u64, zero mov cost);
// x and acts are stored pre-duplicated {v,v} in smem, so the inner loops are
//   1 LDG.64 + 2 LDS.128 + 4 FFMA2  per 8 packed fp32 FMAs.
// Dynamic smem layout (u64 units):
//   acts_dup [512 rows x 10]   (rows padded 8->10 for 16B alignment)   40960 B
//   scratch  [2048]            xs_dup(1024) + gs_dup(8)  -> reused as
//                              part[4][8][64] after the encode sync    16384 B
// ---------------------------------------------------------------------------
#define ACTS_ROW 10
#define SMEM_U64 (D_DICT * ACTS_ROW + 2048)
#define SMEM_BYTES (SMEM_U64 * 8)

__global__ void __launch_bounds__(512, 2)
k_compute(const float* __restrict__ x,
          const float* __restrict__ Wenc,
          const float* __restrict__ Wdec,
          const float* __restrict__ benc,
          const float* __restrict__ bdec) {
    int s = blockIdx.x;
    int n = g_cnt[s]; if (n > CAP) n = CAP;
    int t0 = blockIdx.y * CHUNK;
    if (t0 >= n) return;
    int m = n - t0; if (m > CHUNK) m = CHUNK;

    extern __shared__ __align__(16) u64 sm[];
    u64* acts    = sm;                       // [512][ACTS_ROW]
    u64* scratch = sm + D_DICT * ACTS_ROW;   // 2048 u64
    u64* xs  = scratch;                      // [128][8] dup x
    u64* gsd = scratch + 1024;               // [8] dup gate
    u64* part = scratch;                     // [4][8][64] (aliases xs after encode)
    __shared__ int pr[CHUNK];

    int tid = threadIdx.x;
    if (tid < CHUNK) {
        int j = tid;
        int pair = 0; float gv = 0.0f;
        if (j < m) { pair = g_pair[s * CAP + t0 + j]; gv = g_gv[s * CAP + t0 + j]; }
        pr[j] = pair;
        gsd[j] = pk(gv, gv);
    }
    __syncthreads();

    // Fill xs_dup: coalesced x reads, duplicated stores.
    for (int i = tid; i < D_DATA * CHUNK; i += 512) {
        int j = i >> 7, d = i & 127;
        float v = (j < m) ? x[(pr[j] >> 1) * D_DATA + d] : 0.0f;
        xs[d * CHUNK + j] = pk(v, v);
    }
    __syncthreads();

    // ---------------- Encode ----------------
    {
        int ep = tid & 255;          // e-pair: e = 2ep, 2ep+1
        int th = tid >> 8;           // tokens 4th .. 4th+3
        const u64* W = (const u64*)(Wenc + (size_t)s * D_DATA * D_DICT) + ep;
        u64 bias = __ldg((const u64*)(benc + (size_t)s * D_DICT) + ep);
        u64 a0 = bias, a1 = bias, a2 = bias, a3 = bias;
        const u64* xp = xs + 4 * th;
        #pragma unroll 8
        for (int d = 0; d < D_DATA; d++) {
            u64 w = __ldg(W + d * (D_DICT / 2));
            ulonglong2 x01 = *(const ulonglong2*)(xp + d * CHUNK);
            ulonglong2 x23 = *(const ulonglong2*)(xp + d * CHUNK + 2);
            a0 = fma2(x01.x, w, a0);
            a1 = fma2(x01.y, w, a1);
            a2 = fma2(x23.x, w, a2);
            a3 = fma2(x23.y, w, a3);
        }
        int jb = 4 * th;
        u64 accs[4] = {a0, a1, a2, a3};
        #pragma unroll
        for (int jj = 0; jj < 4; jj++) {
            u64 r = mul2(relu2(accs[jj]), gsd[jb + jj]);
            float lo, hi; upk(lo, hi, r);
            acts[(2 * ep    ) * ACTS_ROW + jb + jj] = pk(lo, lo);
            acts[(2 * ep + 1) * ACTS_ROW + jb + jj] = pk(hi, hi);
        }
    }
    __syncthreads();

    // ---------------- Decode ----------------
    {
        int dp = tid & 63;           // d-pair: d = 2dp, 2dp+1
        int th = (tid >> 6) & 1;     // tokens 4th .. 4th+3
        int g  = tid >> 7;           // e-group: e in [128g, 128g+128)
        const u64* W = (const u64*)(Wdec + (size_t)s * D_DICT * D_DATA) + dp
                     + (size_t)g * 128 * (D_DATA / 2);
        const u64* ap = acts + (size_t)g * 128 * ACTS_ROW + 4 * th;
        u64 b0 = 0, b1 = 0, b2 = 0, b3 = 0;
        #pragma unroll 8
        for (int ee = 0; ee < 128; ee++) {
            u64 w = __ldg(W + ee * (D_DATA / 2));
            ulonglong2 q01 = *(const ulonglong2*)(ap + ee * ACTS_ROW);
            ulonglong2 q23 = *(const ulonglong2*)(ap + ee * ACTS_ROW + 2);
            b0 = fma2(q01.x, w, b0);
            b1 = fma2(q01.y, w, b1);
            b2 = fma2(q23.x, w, b2);
            b3 = fma2(q23.y, w, b3);
        }
        __syncthreads();   // all acts/xs reads done before part overwrites scratch
        int jb = 4 * th;
        u64 accs[4] = {b0, b1, b2, b3};
        #pragma unroll
        for (int jj = 0; jj < 4; jj++)
            part[(g * 8 + jb + jj) * 64 + dp] = accs[jj];
    }
    __syncthreads();

    // Reduce 4 e-group partials + b_dec, write per-pair stage rows (float2).
    {
        int tok = tid >> 6;          // 0..7
        int dp  = tid & 63;
        if (tok < m) {
            u64 sum = add2(add2(part[(0 * 8 + tok) * 64 + dp],
                                part[(1 * 8 + tok) * 64 + dp]),
                           add2(part[(2 * 8 + tok) * 64 + dp],
                                part[(3 * 8 + tok) * 64 + dp]));
            float lo, hi; upk(lo, hi, sum);
            float2 bd = ((const float2*)(bdec + (size_t)s * D_DATA))[dp];
            float2 o; o.x = lo + bd.x; o.y = hi + bd.y;
            ((float2*)g_stage)[(size_t)pr[tok] * (D_DATA / 2) + dp] = o;
        }
    }
}

// ---------------------------------------------------------------------------
// Kernel 3: combine the K=2 staged rows per token into the output (float4),
// and re-zero all counters for the next graph replay.
// ---------------------------------------------------------------------------
__global__ void k_combine(float* __restrict__ out) {
    int i = blockIdx.x * 256 + threadIdx.x;   // 0..32767 float4 units
    const float4* st = (const float4*)g_stage;
    int b = i >> 5, d4 = i & 31;
    float4 a = st[b * 64 + d4];
    float4 c = st[b * 64 + 32 + d4];
    float4 r;
    r.x = a.x + c.x; r.y = a.y + c.y; r.z = a.z + c.z; r.w = a.w + c.w;
    ((float4*)out)[i] = r;
    if (i < N_SAE)  g_cnt[i]  = 0;
    if (i < BATCH)  g_tcnt[i] = 0;
}

// ---------------------------------------------------------------------------
// Launch. Inputs (metadata order): x, gate, W_enc, W_dec, b_enc, b_dec, k
// ---------------------------------------------------------------------------
extern "C" void kernel_launch(void* const* d_in, const int* in_sizes, int n_in,
                              void* d_out, int out_size) {
    const float* x    = (const float*)d_in[0];
    const float* gate = (const float*)d_in[1];
    const float* Wenc = (const float*)d_in[2];
    const float* Wdec = (const float*)d_in[3];
    const float* benc = (const float*)d_in[4];
    const float* bdec = (const float*)d_in[5];
    float* out = (float*)d_out;

    cudaFuncSetAttribute(k_compute, cudaFuncAttributeMaxDynamicSharedMemorySize,
                         SMEM_BYTES);

    k_build<<<16, 512>>>(gate);
    dim3 grid(N_SAE, CAP / CHUNK);
    k_compute<<<grid, 512, SMEM_BYTES>>>(x, Wenc, Wdec, benc, bdec);
    k_combine<<<BATCH * D_DATA / 4 / 256, 256>>>(out);
}

// round 4
// speedup vs baseline: 1.4371x; 1.4371x over previous
#include <cuda_runtime.h>

// Problem constants (fixed by the reference)
#define N_SAE  128
#define D_DATA 128
#define D_DICT 512
#define BATCH  1024
#define CHUNK  8      // tokens per compute CTA
#define NCHUNK 6      // grid.y; cap = 48 tokens/expert (max observed ~28, 8 sigma)

typedef unsigned long long u64;

// Per-pair staged decode output (pair id = token*2 + j), combined by k_combine.
__device__ float g_stage[BATCH * 2 * D_DATA];   // 1 MB

// ---------------- f32x2 packed helpers (sm_103a) ----------------
__device__ __forceinline__ u64 pk(float lo, float hi) {
    u64 r; asm("mov.b64 %0,{%1,%2};" : "=l"(r) : "f"(lo), "f"(hi)); return r;
}
__device__ __forceinline__ void upk(float& lo, float& hi, u64 v) {
    asm("mov.b64 {%0,%1},%2;" : "=f"(lo), "=f"(hi) : "l"(v));
}
__device__ __forceinline__ u64 fma2(u64 a, u64 b, u64 c) {
    u64 d; asm("fma.rn.f32x2 %0,%1,%2,%3;" : "=l"(d) : "l"(a), "l"(b), "l"(c)); return d;
}
__device__ __forceinline__ u64 add2(u64 a, u64 b) {
    u64 d; asm("add.rn.f32x2 %0,%1,%2;" : "=l"(d) : "l"(a), "l"(b)); return d;
}
__device__ __forceinline__ u64 mul2(u64 a, u64 b) {
    u64 d; asm("mul.rn.f32x2 %0,%1,%2;" : "=l"(d) : "l"(a), "l"(b)); return d;
}
__device__ __forceinline__ u64 relu2(u64 v) {
    float lo, hi; upk(lo, hi, v);
    return pk(fmaxf(lo, 0.0f), fmaxf(hi, 0.0f));
}

// ---------------------------------------------------------------------------
// Fused kernel: in-CTA routing scan + encode -> relu -> gate -> decode, staged
// per-pair output. grid = (N_SAE, NCHUNK), 512 threads.
// Routing: scan gate column s (ballot + block prefix) -> rank-ordered token
// list, deterministic. Slot j for staging = #nonzeros with e' < s in the
// token's gate row (1 warp per token).
// ---------------------------------------------------------------------------
__global__ void __launch_bounds__(512, 2)
k_compute(const float* __restrict__ x,
          const float* __restrict__ gate,
          const float* __restrict__ Wenc,
          const float* __restrict__ Wdec,
          const float* __restrict__ benc,
          const float* __restrict__ bdec) {
    int s = blockIdx.x;
    int t0 = blockIdx.y * CHUNK;

    __shared__ __align__(16) float xs[D_DATA][CHUNK];   // x transposed (4 KB)
    __shared__ u64 acts[D_DICT][6];                     // [0..3] used   (24 KB)
    __shared__ u64 part[4][4][D_DATA];                  // partials      (16 KB)
    __shared__ u64 gsp[4];                              // packed gates
    __shared__ int prtok[CHUNK];                        // token ids
    __shared__ int pj[CHUNK];                           // pair ids (token*2+j)
    __shared__ unsigned masks[32];
    __shared__ int pcnt[32];
    __shared__ int ntot;

    int tid  = threadIdx.x;
    int warp = tid >> 5, lane = tid & 31;

    // ---- Routing: column scan of gate[:, s] ----
    float v0 = __ldg(&gate[(size_t)tid * N_SAE + s]);
    float v1 = __ldg(&gate[(size_t)(tid + 512) * N_SAE + s]);
    unsigned m0 = __ballot_sync(0xffffffffu, v0 != 0.0f);
    unsigned m1 = __ballot_sync(0xffffffffu, v1 != 0.0f);
    if (lane == 0) { masks[warp] = m0; masks[16 + warp] = m1; }
    if (tid < CHUNK) { prtok[tid] = 0; ((float*)gsp)[tid] = 0.0f; pj[tid] = 0; }
    __syncthreads();
    if (warp == 0) {
        int c = __popc(masks[lane]);
        int ex = c;
        #pragma unroll
        for (int o = 1; o < 32; o <<= 1) {
            int t = __shfl_up_sync(0xffffffffu, ex, o);
            if (lane >= o) ex += t;
        }
        pcnt[lane] = ex - c;           // exclusive prefix
        if (lane == 31) ntot = ex;     // total count
    }
    __syncthreads();
    int n = ntot;
    if (t0 >= n) return;
    int m = n - t0; if (m > CHUNK) m = CHUNK;

    if (v0 != 0.0f) {
        int r = pcnt[warp] + __popc(m0 & ((1u << lane) - 1));
        if (r >= t0 && r < t0 + CHUNK) {
            prtok[r - t0] = tid; ((float*)gsp)[r - t0] = v0;
        }
    }
    if (v1 != 0.0f) {
        int r = pcnt[16 + warp] + __popc(m1 & ((1u << lane) - 1));
        if (r >= t0 && r < t0 + CHUNK) {
            prtok[r - t0] = tid + 512; ((float*)gsp)[r - t0] = v1;
        }
    }
    __syncthreads();

    // ---- Slot j per token: one warp per token scans the gate row ----
    if (warp < CHUNK) {
        int b = prtok[warp];
        float4 gv = ((const float4*)gate)[(size_t)b * (N_SAE / 4) + lane];
        int e0 = lane * 4;
        int c = (gv.x != 0.0f && e0     < s) + (gv.y != 0.0f && e0 + 1 < s)
              + (gv.z != 0.0f && e0 + 2 < s) + (gv.w != 0.0f && e0 + 3 < s);
        #pragma unroll
        for (int o = 16; o > 0; o >>= 1) c += __shfl_xor_sync(0xffffffffu, c, o);
        if (lane == 0) pj[warp] = b * 2 + c;
    }

    // ---- Load chunk x rows, transposed (coalesced over d) ----
    for (int i = tid; i < D_DATA * CHUNK; i += 512) {
        int j = i >> 7, d = i & 127;
        xs[d][j] = (j < m) ? x[(size_t)prtok[j] * D_DATA + d] : 0.0f;
    }
    __syncthreads();

    // ---------------- Encode ----------------
    {
        int ep = tid & 255;       // e = 2ep, 2ep+1
        int th = tid >> 8;        // tokens 4th .. 4th+3
        const float2* W = (const float2*)(Wenc + (size_t)s * D_DATA * D_DICT) + ep;
        float2 be = ((const float2*)(benc + (size_t)s * D_DICT))[ep];
        u64 a00 = pk(be.x, be.x), a01 = a00;   // e=2ep,   token pairs {0,1}
        u64 a10 = pk(be.y, be.y), a11 = a10;   // e=2ep+1
        #pragma unroll 8
        for (int d = 0; d < D_DATA; d++) {
            float2 w = __ldg(W + d * (D_DICT / 2));
            u64 w0 = pk(w.x, w.x), w1 = pk(w.y, w.y);
            ulonglong2 xp = ((const ulonglong2*)xs[d])[th];  // 4 tokens, 2 pairs
            a00 = fma2(xp.x, w0, a00);
            a01 = fma2(xp.y, w0, a01);
            a10 = fma2(xp.x, w1, a10);
            a11 = fma2(xp.y, w1, a11);
        }
        u64 g0 = gsp[2 * th], g1 = gsp[2 * th + 1];
        acts[2 * ep    ][2 * th    ] = mul2(relu2(a00), g0);
        acts[2 * ep    ][2 * th + 1] = mul2(relu2(a01), g1);
        acts[2 * ep + 1][2 * th    ] = mul2(relu2(a10), g0);
        acts[2 * ep + 1][2 * th + 1] = mul2(relu2(a11), g1);
    }
    __syncthreads();

    // ---------------- Decode ----------------
    {
        int dp = tid & 63;         // d = 2dp, 2dp+1
        int th = (tid >> 6) & 1;   // token pairs {2th, 2th+1}
        int g  = tid >> 7;         // e-group 0..3: e in [128g, 128g+128)
        const float2* W = (const float2*)(Wdec + (size_t)s * D_DICT * D_DATA) + dp;
        u64 a00 = 0, a01 = 0, a10 = 0, a11 = 0;
        int e0 = g * 128;
        #pragma unroll 8
        for (int ee = 0; ee < 128; ee++) {
            int e = e0 + ee;
            float2 w = __ldg(W + e * (D_DATA / 2));
            u64 w0 = pk(w.x, w.x), w1 = pk(w.y, w.y);
            ulonglong2 ap = ((const ulonglong2*)acts[e])[th];
            a00 = fma2(ap.x, w0, a00);
            a01 = fma2(ap.y, w0, a01);
            a10 = fma2(ap.x, w1, a10);
            a11 = fma2(ap.y, w1, a11);
        }
        part[g][2 * th    ][2 * dp    ] = a00;
        part[g][2 * th + 1][2 * dp    ] = a01;
        part[g][2 * th    ][2 * dp + 1] = a10;
        part[g][2 * th + 1][2 * dp + 1] = a11;
    }
    __syncthreads();

    // Reduce 4 e-group partials + b_dec, write per-pair stage rows.
    {
        int d  = tid & 127;
        int tp = tid >> 7;         // token pair: tokens 2tp, 2tp+1
        u64 sum = part[0][tp][d];
        #pragma unroll
        for (int g = 1; g < 4; g++) sum = add2(sum, part[g][tp][d]);
        float lo, hi; upk(lo, hi, sum);
        float bd = bdec[s * D_DATA + d];
        int j0 = 2 * tp, j1 = 2 * tp + 1;
        if (j0 < m) g_stage[(size_t)pj[j0] * D_DATA + d] = lo + bd;
        if (j1 < m) g_stage[(size_t)pj[j1] * D_DATA + d] = hi + bd;
    }
}

// ---------------------------------------------------------------------------
// Combine the K=2 staged rows per token into the output (float4).
// ---------------------------------------------------------------------------
__global__ void k_combine(float* __restrict__ out) {
    int i = blockIdx.x * 256 + threadIdx.x;   // 0..32767 float4 units
    const float4* st = (const float4*)g_stage;
    int b = i >> 5, d4 = i & 31;
    float4 a = st[b * 64 + d4];
    float4 c = st[b * 64 + 32 + d4];
    float4 r;
    r.x = a.x + c.x; r.y = a.y + c.y; r.z = a.z + c.z; r.w = a.w + c.w;
    ((float4*)out)[i] = r;
}

// ---------------------------------------------------------------------------
// Launch. Inputs (metadata order): x, gate, W_enc, W_dec, b_enc, b_dec, k
// ---------------------------------------------------------------------------
extern "C" void kernel_launch(void* const* d_in, const int* in_sizes, int n_in,
                              void* d_out, int out_size) {
    const float* x    = (const float*)d_in[0];
    const float* gate = (const float*)d_in[1];
    const float* Wenc = (const float*)d_in[2];
    const float* Wdec = (const float*)d_in[3];
    const float* benc = (const float*)d_in[4];
    const float* bdec = (const float*)d_in[5];
    float* out = (float*)d_out;

    dim3 grid(N_SAE, NCHUNK);
    k_compute<<<grid, 512>>>(x, gate, Wenc, Wdec, benc, bdec);
    k_combine<<<BATCH * D_DATA / 4 / 256, 256>>>(out);
}